// round 7
// baseline (speedup 1.0000x reference)
#include <cuda_runtime.h>

// TemporalDecay: out = h + (1-M)*gamma*(h_fwd - h), gamma = exp(-relu(delta*W + b))
// h_fwd[b,t,j] = h[b, t-(delta-1), j], delta in {1..4} clamped to t+1, d = j % 64.
//
// R7: transpose mapping -> one thread per (row, d), k-loop over the 4 feature
// replicas as scalars.
//  * delta/M/gather-predicate are UNIFORM across k: loaded once per thread.
//  * warp lanes = consecutive d -> all stream accesses are full 128B wavefronts.
//  * gather lanes are stride-1 (split into delta-runs) -> ~4x fewer partial
//    L1 wavefronts than the stride-16B float4 mapping.
//  * coef = (1-m)*min(exp(-(d*W+b)),1); delta==1 needs no gather (hf==ha).

#define B_    32
#define T_    2048
#define D_    64
#define KD_   256
#define TPB   256
#define NTHR  (B_ * T_ * D_)   // 4,194,304

__global__ __launch_bounds__(TPB, 8)
void temporal_decay_kernel(const float* __restrict__ h,
                           const float* __restrict__ dlt,
                           const float* __restrict__ m,
                           const float* __restrict__ W,
                           const float* __restrict__ Bv,
                           float* __restrict__ out)
{
    const int i   = blockIdx.x * TPB + threadIdx.x;
    const int d   = i & (D_ - 1);
    const int row = i >> 6;              // b*T + t

    // Uniform-per-thread small operands.
    const float df = dlt[i];             // [row, d] — lanes consecutive: 128B wf
    const float mf = m[i];
    const int   di = (int)df;
    const float a  = 1.0f - mf;
    const bool  need = (mf == 0.0f) && (di > 1);

    const int base  = row * KD_ + d;                 // own element, k=0
    const int gbase = (row - di + 1) * KD_ + d;      // gather row base

    // W/b per k (read-only, tiny, L1-resident).
    const float w0 = W[d],          b0 = Bv[d];
    const float w1 = W[d + 64],     b1 = Bv[d + 64];
    const float w2 = W[d + 128],    b2 = Bv[d + 128];
    const float w3 = W[d + 192],    b3 = Bv[d + 192];

    const float c0 = a * fminf(__expf(-fmaf(df, w0, b0)), 1.0f);
    const float c1 = a * fminf(__expf(-fmaf(df, w1, b1)), 1.0f);
    const float c2 = a * fminf(__expf(-fmaf(df, w2, b2)), 1.0f);
    const float c3 = a * fminf(__expf(-fmaf(df, w3, b3)), 1.0f);

    // Own values (each instr: 32 consecutive lanes -> one 128B wavefront).
    const float h0 = h[base];
    const float h1 = h[base + 64];
    const float h2 = h[base + 128];
    const float h3 = h[base + 192];

    // Gathers: stride-1 active-lane runs, one shared predicate.
    const float f0 = need ? __ldg(h + gbase)       : h0;
    const float f1 = need ? __ldg(h + gbase + 64)  : h1;
    const float f2 = need ? __ldg(h + gbase + 128) : h2;
    const float f3 = need ? __ldg(h + gbase + 192) : h3;

    out[base]       = fmaf(c0, f0 - h0, h0);
    out[base + 64]  = fmaf(c1, f1 - h1, h1);
    out[base + 128] = fmaf(c2, f2 - h2, h2);
    out[base + 192] = fmaf(c3, f3 - h3, h3);
}

extern "C" void kernel_launch(void* const* d_in, const int* in_sizes, int n_in,
                              void* d_out, int out_size)
{
    const float* h_a    = (const float*)d_in[0];
    const float* deltas = (const float*)d_in[1];
    const float* M      = (const float*)d_in[2];
    const float* W      = (const float*)d_in[3];
    const float* bvec   = (const float*)d_in[4];
    float* out          = (float*)d_out;

    const int blocks = NTHR / TPB;   // 16384

    temporal_decay_kernel<<<blocks, TPB>>>(
        h_a, deltas, M, W, bvec, out);
}

// round 8
// speedup vs baseline: 1.0061x; 1.0061x over previous
#include <cuda_runtime.h>

// TemporalDecay: out = h + (1-M)*gamma*(h_fwd - h), gamma = exp(-relu(delta*W + b))
// h_fwd[b,t,j] = h[b, t-(delta-1), j], delta in {1..4} clamped to t+1, d = j % 64.
//
// R8 = R7 (transposed mapping: one thread per (row,d), scalar k-loop) + cache
// policy tuning:
//  * out stores use __stcs (evict-first): 67MB never re-read, keep L2 for h.
//  * delta/M loads use __ldcs (read-once streams, 34MB): don't evict h lines.
//  * h keeps default policy (only reused stream: own row + history gathers).

#define B_    32
#define T_    2048
#define D_    64
#define KD_   256
#define TPB   256
#define NTHR  (B_ * T_ * D_)   // 4,194,304

__global__ __launch_bounds__(TPB, 8)
void temporal_decay_kernel(const float* __restrict__ h,
                           const float* __restrict__ dlt,
                           const float* __restrict__ m,
                           const float* __restrict__ W,
                           const float* __restrict__ Bv,
                           float* __restrict__ out)
{
    const int i   = blockIdx.x * TPB + threadIdx.x;
    const int d   = i & (D_ - 1);
    const int row = i >> 6;              // b*T + t

    // Uniform-per-thread small operands (read-once -> evict-first).
    const float df = __ldcs(dlt + i);
    const float mf = __ldcs(m + i);
    const int   di = (int)df;
    const float a  = 1.0f - mf;
    const bool  need = (mf == 0.0f) && (di > 1);

    const int base  = row * KD_ + d;                 // own element, k=0
    const int gbase = (row - di + 1) * KD_ + d;      // gather row base

    // W/b per k (tiny, L1-resident).
    const float w0 = W[d],          b0 = Bv[d];
    const float w1 = W[d + 64],     b1 = Bv[d + 64];
    const float w2 = W[d + 128],    b2 = Bv[d + 128];
    const float w3 = W[d + 192],    b3 = Bv[d + 192];

    // coef = (1-m) * min(exp(-(d*W+b)), 1)   (== (1-m)*exp(-relu(.)))
    const float c0 = a * fminf(__expf(-fmaf(df, w0, b0)), 1.0f);
    const float c1 = a * fminf(__expf(-fmaf(df, w1, b1)), 1.0f);
    const float c2 = a * fminf(__expf(-fmaf(df, w2, b2)), 1.0f);
    const float c3 = a * fminf(__expf(-fmaf(df, w3, b3)), 1.0f);

    // Own values: each instr is one full 128B wavefront.
    const float h0 = h[base];
    const float h1 = h[base + 64];
    const float h2 = h[base + 128];
    const float h3 = h[base + 192];

    // Gathers: stride-1 active-lane runs, one shared predicate; delta==1 needs
    // no gather (hf == ha exactly).
    const float f0 = need ? __ldg(h + gbase)       : h0;
    const float f1 = need ? __ldg(h + gbase + 64)  : h1;
    const float f2 = need ? __ldg(h + gbase + 128) : h2;
    const float f3 = need ? __ldg(h + gbase + 192) : h3;

    __stcs(out + base,       fmaf(c0, f0 - h0, h0));
    __stcs(out + base + 64,  fmaf(c1, f1 - h1, h1));
    __stcs(out + base + 128, fmaf(c2, f2 - h2, h2));
    __stcs(out + base + 192, fmaf(c3, f3 - h3, h3));
}

extern "C" void kernel_launch(void* const* d_in, const int* in_sizes, int n_in,
                              void* d_out, int out_size)
{
    const float* h_a    = (const float*)d_in[0];
    const float* deltas = (const float*)d_in[1];
    const float* M      = (const float*)d_in[2];
    const float* W      = (const float*)d_in[3];
    const float* bvec   = (const float*)d_in[4];
    float* out          = (float*)d_out;

    const int blocks = NTHR / TPB;   // 16384

    temporal_decay_kernel<<<blocks, TPB>>>(
        h_a, deltas, M, W, bvec, out);
}